// round 16
// baseline (speedup 1.0000x reference)
#include <cuda_runtime.h>
#include <cuda_bf16.h>
#include <cstdint>
#include <math.h>

#define BB 4096
#define FF 256

// ---------------- scratch (device globals) ----------------------------------
// GEMM operands CHUNK-MAJOR + SWIZZLED:
//   (row, col) -> slab kc=col>>6, 128B row-chunk, quad q=((col>>3)&7)^(row&7)
__device__ __nv_bfloat16 d_s_hi[BB*FF],  d_s_lo[BB*FF];
__device__ __nv_bfloat16 d_g_hi[BB*FF],  d_g_lo[BB*FF];
__device__ __nv_bfloat16 d_c_hi[BB*FF],  d_c_lo[BB*FF];
__device__ __nv_bfloat16 d_wp_hi[FF*FF], d_wp_lo[FF*FF];
__device__ __nv_bfloat16 d_wih_hi[3*FF*FF], d_wih_lo[3*FF*FF];
__device__ __nv_bfloat16 d_whh_hi[3*FF*FF], d_whh_lo[3*FF*FF];
__device__ float g_gh[BB*3*FF];
__device__ float g_gi[BB*3*FF];
__device__ int   g_cnt[BB];
__device__ int   ctx_done[64];

// ---------------- helpers ----------------------------------------------------
__device__ __forceinline__ uint32_t smem_u32(const void* p) {
    uint32_t a;
    asm("{ .reg .u64 t; cvta.to.shared.u64 t, %1; cvt.u32.u64 %0, t; }" : "=r"(a) : "l"(p));
    return a;
}
__device__ __forceinline__ void mbar_init(uint32_t a, uint32_t cnt) {
    asm volatile("mbarrier.init.shared.b64 [%0], %1;" :: "r"(a), "r"(cnt) : "memory");
}
__device__ __forceinline__ void mbar_wait(uint32_t a, int parity) {
    asm volatile(
        "{\n\t.reg .pred P;\n\t"
        "LAB_%=:\n\t"
        "mbarrier.try_wait.parity.acquire.cta.shared::cta.b64 P, [%0], %1, 0x989680;\n\t"
        "@!P bra LAB_%=;\n\t}"
        :: "r"(a), "r"((uint32_t)parity) : "memory");
}
__device__ __forceinline__ void cp16(uint32_t dst, const void* src) {
    asm volatile("cp.async.cg.shared.global [%0], [%1], 16;" :: "r"(dst), "l"(src));
}
__device__ __forceinline__ void cp_commit() {
    asm volatile("cp.async.commit_group;" ::: "memory");
}
template<int n>
__device__ __forceinline__ void cp_wait() {
    asm volatile("cp.async.wait_group %0;" :: "n"(n) : "memory");
}
__device__ __forceinline__ void ldsm4(uint32_t* r, uint32_t addr) {
    asm volatile("ldmatrix.sync.aligned.m8n8.x4.shared.b16 {%0,%1,%2,%3}, [%4];"
        : "=r"(r[0]), "=r"(r[1]), "=r"(r[2]), "=r"(r[3]) : "r"(addr));
}
__device__ __forceinline__ void mma16816(float* d, const uint32_t* a, uint32_t b0, uint32_t b1) {
    asm volatile("mma.sync.aligned.m16n8k16.row.col.f32.bf16.bf16.f32 "
        "{%0,%1,%2,%3}, {%4,%5,%6,%7}, {%8,%9}, {%0,%1,%2,%3};"
        : "+f"(d[0]), "+f"(d[1]), "+f"(d[2]), "+f"(d[3])
        : "r"(a[0]), "r"(a[1]), "r"(a[2]), "r"(a[3]), "r"(b0), "r"(b1));
}
__device__ __forceinline__ size_t sw_idx(int row, int col, int R) {
    int kc = col >> 6;
    int q  = ((col >> 3) & 7) ^ (row & 7);
    return (((size_t)kc * R + row) << 6) + (q << 3) + (col & 7);
}
__device__ __forceinline__ void split_store_sw(float v, __nv_bfloat16* hi, __nv_bfloat16* lo,
                                               int row, int col, int R) {
    size_t i = sw_idx(row, col, R);
    __nv_bfloat16 h = __float2bfloat16(v);
    hi[i] = h;
    lo[i] = __float2bfloat16(v - __bfloat162float(h));
}

// ---------------- kernel P: bf16 hi/lo prep (swizzled layouts) ---------------
__global__ __launch_bounds__(256) void prep(const float* __restrict__ Wp,
                                            const float* __restrict__ Wih,
                                            const float* __restrict__ Whh,
                                            const float* __restrict__ g)
{
    if (blockIdx.x == 0 && threadIdx.x < 64) ctx_done[threadIdx.x] = 0;
    int i = blockIdx.x * 256 + threadIdx.x;
    int row = i >> 8, col = i & 255;
    if (i < FF*FF)      split_store_sw(Wp[i],  d_wp_hi,  d_wp_lo,  row, col, FF);
    if (i < 3*FF*FF) {  split_store_sw(Wih[i], d_wih_hi, d_wih_lo, row, col, 3*FF);
                        split_store_sw(Whh[i], d_whh_hi, d_whh_lo, row, col, 3*FF); }
    if (i < BB*FF)      split_store_sw(g[i],   d_g_hi,   d_g_lo,   row, col, BB);
}

// ---------------- kernel A: warp-per-graph attention pooling -----------------
__global__ __launch_bounds__(256) void attn_pool(
    const float* __restrict__ node, const float* __restrict__ g,
    const int*  __restrict__ seg,   const float* __restrict__ Wl,
    const float* __restrict__ bl,   int N)
{
    __shared__ float wlA[FF], wlB[FF];
    int t = threadIdx.x, warp = t >> 5, lane = t & 31;
    wlA[t] = Wl[t];
    wlB[t] = Wl[FF + t];
    __syncthreads();

    int b = blockIdx.x * 8 + warp;
    float4 wg0 = ((const float4*)wlA)[lane];
    float4 wg1 = ((const float4*)wlA)[32 + lane];
    float4 w0  = ((const float4*)wlB)[lane];
    float4 w1  = ((const float4*)wlB)[32 + lane];

    const float4* grow = (const float4*)(g + (size_t)b * FF);
    float4 gx0 = grow[lane], gx1 = grow[32 + lane];
    float c1p = fmaxf(gx0.x,0.f)*wg0.x + fmaxf(gx0.y,0.f)*wg0.y
              + fmaxf(gx0.z,0.f)*wg0.z + fmaxf(gx0.w,0.f)*wg0.w
              + fmaxf(gx1.x,0.f)*wg1.x + fmaxf(gx1.y,0.f)*wg1.y
              + fmaxf(gx1.z,0.f)*wg1.z + fmaxf(gx1.w,0.f)*wg1.w;
    #pragma unroll
    for (int o = 16; o; o >>= 1) c1p += __shfl_xor_sync(0xffffffffu, c1p, o);

    int lo = 0;
    if (lane < 2) {
        int target = b + lane, hi = N;
        while (lo < hi) { int mid = (lo + hi) >> 1; if (seg[mid] < target) lo = mid + 1; else hi = mid; }
    }
    int start = __shfl_sync(0xffffffffu, lo, 0);
    int end   = __shfl_sync(0xffffffffu, lo, 1);
    if (lane == 0) g_cnt[b] = end - start;

    if (start == end) {
        #pragma unroll
        for (int k = 0; k < 4; k++) {
            split_store_sw(0.f, d_s_hi, d_s_lo, b, 4*lane + k,       BB);
            split_store_sw(0.f, d_s_hi, d_s_lo, b, 128 + 4*lane + k, BB);
        }
        return;
    }

    float c1 = c1p + bl[0];
    float4 A0 = make_float4(0.f,0.f,0.f,0.f), A1 = make_float4(0.f,0.f,0.f,0.f);
    float ssum = 0.f;

    for (int i = start; i < end; i += 2) {
        bool v2 = (i + 1) < end;
        const float4* rA = (const float4*)(node + (size_t)i * FF);
        const float4* rB = (const float4*)(node + (size_t)(v2 ? i + 1 : i) * FF);
        float4 x0 = rA[lane], x1 = rA[32 + lane];
        float4 y0 = rB[lane], y1 = rB[32 + lane];
        float d1 = x0.x*w0.x + x0.y*w0.y + x0.z*w0.z + x0.w*w0.w
                 + x1.x*w1.x + x1.y*w1.y + x1.z*w1.z + x1.w*w1.w;
        float d2 = y0.x*w0.x + y0.y*w0.y + y0.z*w0.z + y0.w*w0.w
                 + y1.x*w1.x + y1.y*w1.y + y1.z*w1.z + y1.w*w1.w;
        #pragma unroll
        for (int o = 16; o; o >>= 1) {
            d1 += __shfl_xor_sync(0xffffffffu, d1, o);
            d2 += __shfl_xor_sync(0xffffffffu, d2, o);
        }
        float z1 = c1 + d1; z1 = z1 > 0.f ? z1 : 0.01f * z1;
        float z2 = c1 + d2; z2 = z2 > 0.f ? z2 : 0.01f * z2;
        float e1 = __expf(z1);
        float e2 = v2 ? __expf(z2) : 0.f;
        ssum += e1 + e2;
        A0.x += e1*x0.x + e2*y0.x;  A0.y += e1*x0.y + e2*y0.y;
        A0.z += e1*x0.z + e2*y0.z;  A0.w += e1*x0.w + e2*y0.w;
        A1.x += e1*x1.x + e2*y1.x;  A1.y += e1*x1.y + e2*y1.y;
        A1.z += e1*x1.z + e2*y1.z;  A1.w += e1*x1.w + e2*y1.w;
    }

    float inv = 1.f / ssum;
    split_store_sw(A0.x*inv, d_s_hi, d_s_lo, b, 4*lane + 0, BB);
    split_store_sw(A0.y*inv, d_s_hi, d_s_lo, b, 4*lane + 1, BB);
    split_store_sw(A0.z*inv, d_s_hi, d_s_lo, b, 4*lane + 2, BB);
    split_store_sw(A0.w*inv, d_s_hi, d_s_lo, b, 4*lane + 3, BB);
    split_store_sw(A1.x*inv, d_s_hi, d_s_lo, b, 128 + 4*lane + 0, BB);
    split_store_sw(A1.y*inv, d_s_hi, d_s_lo, b, 128 + 4*lane + 1, BB);
    split_store_sw(A1.z*inv, d_s_hi, d_s_lo, b, 128 + 4*lane + 2, BB);
    split_store_sw(A1.w*inv, d_s_hi, d_s_lo, b, 128 + 4*lane + 3, BB);
}

// ---------------- 64x128-tile GEMM core (bulk B; A via bulk or cp.async) -----
// 8 warps as 2(m) x 4(n): warp tile 32x32. K'=768 sweep in 12 BK=64 chunks.
// ACG=true: A fed by per-thread cp.async (generic proxy; needed when A was
// written by another CTA in the same kernel). A post-wait __syncthreads makes
// every thread's cp.async completion visible block-wide BEFORE any ldsm
// (cp.async.wait_group is per-thread only -- this was the R15 NaN bug).
#define NSTAGE 4
#define A_BYTES 8192
#define B_BYTES 16384
#define STAGE_SZ (A_BYTES + B_BYTES)        // 24576
#define MBAR_OFF (NSTAGE * STAGE_SZ)        // 98304
#define GSMEM    (MBAR_OFF + 64)

template<bool ACG>
__device__ __forceinline__ void run_gemm64(
    const __nv_bfloat16* __restrict__ Ah, const __nv_bfloat16* __restrict__ Al,
    const __nv_bfloat16* __restrict__ Bh, const __nv_bfloat16* __restrict__ Bl,
    int m0, int j0, int RB, uint32_t smem, float acc[2][4][4])
{
    const int NCH = 12;
    uint32_t mbar = smem + MBAR_OFF;
    int t = threadIdx.x, wid = t >> 5, lane = t & 31;
    int warp_m = wid & 1, warp_n = wid >> 1;

    if (t == 0) {
        #pragma unroll
        for (int s = 0; s < NSTAGE; s++) mbar_init(mbar + s * 8, 1);
    }
    __syncthreads();

    auto issue = [&](int gc, int st) {
        int p = gc >> 2, kc = gc & 3;
        const __nv_bfloat16* As = (p == 1) ? Al : Ah;
        const __nv_bfloat16* Bs = (p == 2) ? Bl : Bh;
        const __nv_bfloat16* srcA = As + (((size_t)kc * BB + m0) << 6);
        const __nv_bfloat16* srcB = Bs + (((size_t)kc * RB + j0) << 6);
        uint32_t dA = smem + st * STAGE_SZ, dB = dA + A_BYTES, mb = mbar + st * 8;
        if (t == 0) {
            asm volatile("fence.proxy.async.shared::cta;" ::: "memory");
            asm volatile("mbarrier.arrive.expect_tx.shared.b64 _, [%0], %1;"
                         :: "r"(mb), "r"(ACG ? (uint32_t)B_BYTES : (uint32_t)(A_BYTES + B_BYTES)) : "memory");
            if (!ACG)
                asm volatile("cp.async.bulk.shared::cluster.global.mbarrier::complete_tx::bytes [%0], [%1], %2, [%3];"
                             :: "r"(dA), "l"(srcA), "r"((uint32_t)A_BYTES), "r"(mb) : "memory");
            asm volatile("cp.async.bulk.shared::cluster.global.mbarrier::complete_tx::bytes [%0], [%1], %2, [%3];"
                         :: "r"(dB), "l"(srcB), "r"((uint32_t)B_BYTES), "r"(mb) : "memory");
        }
        if (ACG) {
            // gmem slab is pre-swizzled: straight 16B copies
            cp16(dA + (uint32_t)t * 16,         srcA + (size_t)t * 8);
            cp16(dA + (uint32_t)(t + 256) * 16, srcA + (size_t)(t + 256) * 8);
            cp_commit();
        }
    };

    issue(0, 0); issue(1, 1); issue(2, 2);

    int aR = warp_m * 32 + (lane & 15);
    int aH = lane >> 4;
    int bR = warp_n * 32 + lane;

    #pragma unroll 1
    for (int c = 0; c < NCH; c++) {
        int st = c % NSTAGE;
        if (c + 3 < NCH) issue(c + 3, (c + 3) % NSTAGE);
        if (ACG) {
            int rem = (c + 3 < NCH) ? 3 : (NCH - 1 - c);
            if (rem >= 3) cp_wait<3>();
            else if (rem == 2) cp_wait<2>();
            else if (rem == 1) cp_wait<1>();
            else cp_wait<0>();
        }
        mbar_wait(mbar + st * 8, (c / NSTAGE) & 1);
        if (ACG) __syncthreads();   // make ALL threads' cp.async for chunk c
                                    // visible block-wide before ldsm (fix)

        uint32_t bA = smem + st * STAGE_SZ, bB = bA + A_BYTES;
        #pragma unroll
        for (int ks = 0; ks < 4; ks++) {
            uint32_t a[2][4];
            #pragma unroll
            for (int mi = 0; mi < 2; mi++) {
                int r = aR + mi * 16;
                ldsm4(a[mi], bA + (uint32_t)(r * 128 + (((2*ks + aH) ^ (r & 7)) << 4)));
            }
            uint32_t bb0[4], bb1[4];
            ldsm4(bb0, bB + (uint32_t)(bR * 128 + (((2*ks    ) ^ (bR & 7)) << 4)));
            ldsm4(bb1, bB + (uint32_t)(bR * 128 + (((2*ks + 1) ^ (bR & 7)) << 4)));
            #pragma unroll
            for (int mi = 0; mi < 2; mi++)
                #pragma unroll
                for (int ni = 0; ni < 4; ni++)
                    mma16816(acc[mi][ni], a[mi], bb0[ni], bb1[ni]);
        }
        __syncthreads();            // stage buffer free for refill
    }
}

__device__ __forceinline__ void epi_store_raw(float* __restrict__ out,
                                              int m0, int j0, float acc[2][4][4])
{
    int t = threadIdx.x, wid = t >> 5, lane = t & 31;
    int warp_m = wid & 1, warp_n = wid >> 1;
    int colBase = warp_n * 32 + (lane & 3) * 2;
    int rowBase = m0 + warp_m * 32 + (lane >> 2);
    #pragma unroll
    for (int mi = 0; mi < 2; mi++)
        #pragma unroll
        for (int ni = 0; ni < 4; ni++) {
            int col = colBase + ni * 8;
            #pragma unroll
            for (int half = 0; half < 2; half++) {
                int row = rowBase + mi * 16 + half * 8;
                *(float2*)(out + (size_t)row * (3*FF) + j0 + col) =
                    make_float2(acc[mi][ni][half*2], acc[mi][ni][half*2+1]);
            }
        }
}

// ---------------- gh GEMM (fork stream, overlaps attention) ------------------
__global__ __launch_bounds__(256, 2) void gemm_gh()
{
    extern __shared__ __align__(128) char sm[];
    float acc[2][4][4] = {};
    int m0 = blockIdx.x * 64, j0 = blockIdx.y * 128;
    run_gemm64<false>(d_g_hi, d_g_lo, d_whh_hi, d_whh_lo, m0, j0, 3*FF, smem_u32(sm), acc);
    epi_store_raw(g_gh, m0, j0, acc);
}

// ---------------- fused ctx + gi with device-side dependency -----------------
// blocks 0..127   : ctx tile (mblk=bid>>1, j0=(bid&1)*128) -> d_c, flag mblk
// blocks 128..511 : gi tile  (mblk=b2&63,  j0=(b2>>6)*128), spins on flag
__global__ __launch_bounds__(256, 2) void ctx_gi(const float* __restrict__ bp)
{
    extern __shared__ __align__(128) char sm[];
    uint32_t smem = smem_u32(sm);
    int bid = blockIdx.x;
    float acc[2][4][4] = {};

    if (bid < 128) {
        int mblk = bid >> 1, j0 = (bid & 1) * 128, m0 = mblk * 64;
        run_gemm64<false>(d_s_hi, d_s_lo, d_wp_hi, d_wp_lo, m0, j0, FF, smem, acc);

        int t = threadIdx.x, wid = t >> 5, lane = t & 31;
        int warp_m = wid & 1, warp_n = wid >> 1;
        int colBase = j0 + warp_n * 32 + (lane & 3) * 2;
        int rowBase = m0 + warp_m * 32 + (lane >> 2);
        #pragma unroll
        for (int mi = 0; mi < 2; mi++)
            #pragma unroll
            for (int ni = 0; ni < 4; ni++) {
                int col = colBase + ni * 8;
                #pragma unroll
                for (int half = 0; half < 2; half++) {
                    int row = rowBase + mi * 16 + half * 8;
                    float v0 = acc[mi][ni][half*2 + 0];
                    float v1 = acc[mi][ni][half*2 + 1];
                    if (g_cnt[row] > 0) { v0 += bp[col]; v1 += bp[col + 1]; }
                    v0 = v0 > 0.f ? v0 : expm1f(v0);
                    v1 = v1 > 0.f ? v1 : expm1f(v1);
                    split_store_sw(v0, d_c_hi, d_c_lo, row, col,     BB);
                    split_store_sw(v1, d_c_hi, d_c_lo, row, col + 1, BB);
                }
            }
        __threadfence();
        __syncthreads();
        if (threadIdx.x == 0) atomicAdd(&ctx_done[mblk], 1);
    } else {
        int b2 = bid - 128;
        int mblk = b2 & 63, j0 = (b2 >> 6) * 128, m0 = mblk * 64;
        if (threadIdx.x == 0) {
            while (atomicAdd(&ctx_done[mblk], 0) < 2) { }
            __threadfence();
        }
        __syncthreads();
        run_gemm64<true>(d_c_hi, d_c_lo, d_wih_hi, d_wih_lo, m0, j0, 3*FF, smem, acc);
        epi_store_raw(g_gi, m0, j0, acc);
    }
}

// ---------------- GRU combine ------------------------------------------------
__global__ __launch_bounds__(256) void gru_combine(
    const float* __restrict__ gfeats, const float* __restrict__ bih,
    const float* __restrict__ bhh,    float* __restrict__ out)
{
    int b = blockIdx.x, j = threadIdx.x;
    size_t r3 = (size_t)b * (3 * FF);
    float ir  = g_gi[r3 + j]        + bih[j];
    float iz  = g_gi[r3 + 256 + j]  + bih[256 + j];
    float in_ = g_gi[r3 + 512 + j]  + bih[512 + j];
    float hr  = g_gh[r3 + j]        + bhh[j];
    float hz  = g_gh[r3 + 256 + j]  + bhh[256 + j];
    float hn  = g_gh[r3 + 512 + j]  + bhh[512 + j];
    float r  = 1.f / (1.f + __expf(-(ir + hr)));
    float zg = 1.f / (1.f + __expf(-(iz + hz)));
    float nn = tanhf(in_ + r * hn);
    float gv = gfeats[(size_t)b * FF + j];
    out[(size_t)b * FF + j] = (1.f - zg) * nn + zg * gv;
}

// ---------------- launch ----------------------------------------------------
extern "C" void kernel_launch(void* const* d_in, const int* in_sizes, int n_in,
                              void* d_out, int out_size)
{
    const float* node = (const float*)d_in[0];
    const float* g    = (const float*)d_in[1];
    const int*   seg  = (const int*)  d_in[2];
    const float* Wl   = (const float*)d_in[3];
    const float* bl   = (const float*)d_in[4];
    const float* Wp   = (const float*)d_in[5];
    const float* bp   = (const float*)d_in[6];
    const float* Wih  = (const float*)d_in[7];
    const float* Whh  = (const float*)d_in[8];
    const float* bih  = (const float*)d_in[9];
    const float* bhh  = (const float*)d_in[10];
    float* out = (float*)d_out;
    int N = in_sizes[2];

    static int inited = 0;
    static cudaStream_t s_fork = 0;
    static cudaEvent_t evA = 0, evP = 0, evB = 0;
    if (!inited) {
        if (cudaStreamCreateWithFlags(&s_fork, cudaStreamNonBlocking) != cudaSuccess) s_fork = 0;
        cudaEventCreateWithFlags(&evA, cudaEventDisableTiming);
        cudaEventCreateWithFlags(&evP, cudaEventDisableTiming);
        cudaEventCreateWithFlags(&evB, cudaEventDisableTiming);
        inited = 1;
    }

    cudaFuncSetAttribute(gemm_gh, cudaFuncAttributeMaxDynamicSharedMemorySize, GSMEM);
    cudaFuncSetAttribute(ctx_gi,  cudaFuncAttributeMaxDynamicSharedMemorySize, GSMEM);

    // fork: prep -> gh on side stream (independent of attention)
    cudaEventRecord(evA, 0);
    cudaStreamWaitEvent(s_fork, evA, 0);
    prep<<<(BB * FF) / 256, 256, 0, s_fork>>>(Wp, Wih, Whh, g);
    cudaEventRecord(evP, s_fork);
    gemm_gh<<<dim3(64, 6), 256, GSMEM, s_fork>>>();
    cudaEventRecord(evB, s_fork);

    // main: attention runs concurrent with prep+gh
    attn_pool<<<BB / 8, 256>>>(node, g, seg, Wl, bl, N);

    // ctx+gi needs attn (stream order) + prep (evP)
    cudaStreamWaitEvent(0, evP, 0);
    ctx_gi<<<512, 256, GSMEM>>>(bp);

    // gru needs gh too (evB)
    cudaStreamWaitEvent(0, evB, 0);
    gru_combine<<<BB, 256>>>(g, bih, bhh, out);
}